// round 10
// baseline (speedup 1.0000x reference)
#include <cuda_runtime.h>
#include <cuda_fp16.h>
#include <cstdint>

#define Nn 8
#define CK 128
#define CV 512
#define Qn 900
#define Mn 7200
#define QM (Qn*Mn)
#define OUT_PER_N (1024*900)
#define SCALE 0.08838834764831845f   // 1/sqrt(128)

// Scratch (__device__ globals; allocation-free rule)
__device__ __align__(16) __half g_p[(size_t)Nn * QM + 64];        // exp(aff) fp16
__device__ __align__(16) __half g_mvh[(size_t)Nn * CV * Mn + 64]; // mv * winv fp16
__device__ __align__(16) __half g_qkH[Nn * CK * Qn + 64];
__device__ __align__(16) __half g_qkL[Nn * CK * Qn + 64];
__device__ __align__(16) __half g_mkH[Nn * CK * Mn + 128];
__device__ float g_sum[Nn * Mn];
__device__ float g_winv[Nn * Mn];

__device__ __forceinline__ uint32_t s2u(const void* p) {
    return (uint32_t)__cvta_generic_to_shared(p);
}
__device__ __forceinline__ void ldsm4(uint32_t* r, uint32_t a) {
    asm volatile("ldmatrix.sync.aligned.m8n8.x4.shared.b16 {%0,%1,%2,%3},[%4];"
                 : "=r"(r[0]), "=r"(r[1]), "=r"(r[2]), "=r"(r[3]) : "r"(a));
}
__device__ __forceinline__ void ldsm4t(uint32_t* r, uint32_t a) {
    asm volatile("ldmatrix.sync.aligned.m8n8.x4.trans.shared.b16 {%0,%1,%2,%3},[%4];"
                 : "=r"(r[0]), "=r"(r[1]), "=r"(r[2]), "=r"(r[3]) : "r"(a));
}
__device__ __forceinline__ void hmma(float* d, const uint32_t* a, const uint32_t* b) {
    asm volatile("mma.sync.aligned.m16n8k16.row.col.f32.f16.f16.f32 "
                 "{%0,%1,%2,%3},{%4,%5,%6,%7},{%8,%9},{%0,%1,%2,%3};"
                 : "+f"(d[0]), "+f"(d[1]), "+f"(d[2]), "+f"(d[3])
                 : "r"(a[0]), "r"(a[1]), "r"(a[2]), "r"(a[3]), "r"(b[0]), "r"(b[1]));
}
__device__ __forceinline__ void cpa16(void* dst, const void* src) {
    asm volatile("cp.async.cg.shared.global [%0],[%1],16;" :: "r"(s2u(dst)), "l"(src));
}
__device__ __forceinline__ void cpa16z(void* dst, const void* src, bool pred) {
    int sz = pred ? 16 : 0;   // src-size 0 -> 16B of zero-fill in smem
    asm volatile("cp.async.cg.shared.global [%0],[%1],16,%2;" :: "r"(s2u(dst)), "l"(src), "r"(sz));
}
__device__ __forceinline__ void cpa8(void* dst, const void* src) {
    asm volatile("cp.async.ca.shared.global [%0],[%1],8;" :: "r"(s2u(dst)), "l"(src));
}
#define CP_COMMIT() asm volatile("cp.async.commit_group;")

// ---------------------------------------------------------------------------
// k_prep (merged K0 + k_split): qk hi/lo split, mk fp16 cvt, q_val copy,
// g_sum zeroing — one launch.
// ---------------------------------------------------------------------------
#define QK4 (Nn * CK * Qn / 4)          // 230400
#define MK4 (Nn * CK * Mn / 4)          // 1843200
#define QV4 (Nn * CV * Qn / 4)          // 921600
__global__ void k_prep(const float4* __restrict__ qk, const float4* __restrict__ mk,
                       const float4* __restrict__ qv, float* __restrict__ out) {
    int i = blockIdx.x * blockDim.x + threadIdx.x;
    if (i < Nn * Mn) g_sum[i] = 0.f;
    if (i < QK4) {
        float4 v = qk[i];
        float fx[4] = {v.x, v.y, v.z, v.w};
        __half h[4], l[4];
        #pragma unroll
        for (int e = 0; e < 4; ++e) {
            h[e] = __float2half_rn(fx[e]);
            l[e] = __float2half_rn(fx[e] - __half2float(h[e]));
        }
        __half2* dh = reinterpret_cast<__half2*>(g_qkH + (size_t)i * 4);
        __half2* dl = reinterpret_cast<__half2*>(g_qkL + (size_t)i * 4);
        dh[0] = __halves2half2(h[0], h[1]); dh[1] = __halves2half2(h[2], h[3]);
        dl[0] = __halves2half2(l[0], l[1]); dl[1] = __halves2half2(l[2], l[3]);
    } else if (i < QK4 + MK4) {
        int j = i - QK4;
        float4 v = mk[j];
        __half2* dh = reinterpret_cast<__half2*>(g_mkH + (size_t)j * 4);
        dh[0] = __floats2half2_rn(v.x, v.y);
        dh[1] = __floats2half2_rn(v.z, v.w);
    } else if (i < QK4 + MK4 + QV4) {
        int j = i - QK4 - MK4;
        int n = j / ((CV * Qn) / 4);
        int r = j - n * ((CV * Qn) / 4);
        float4 v = qv[j];
        *reinterpret_cast<float4*>(out + (size_t)n * OUT_PER_N + (size_t)r * 4) = v;
    }
}

// ---------------------------------------------------------------------------
// K1: g_p = exp(SCALE * qk^T mk), fp16x2 (q-side hi/lo vs mk-hi), cp.async.
// Fused column sums of the ROUNDED fp16 values. (unchanged from R8)
// Block 64(q) x 128(m); 8 warps = 2(q) x 4(m).
// ---------------------------------------------------------------------------
#define PQ1 72
#define PM1 136
__global__ void __launch_bounds__(256) k1_aff() {
    __shared__ __half SqH[4][32 * PQ1], SqL[4][32 * PQ1];
    __shared__ __half SmH[4][32 * PM1];

    const int tid = threadIdx.x, lane = tid & 31, wid = tid >> 5;
    const int n = blockIdx.z, qB = blockIdx.y * 64, mB = blockIdx.x * 128;
    const __half* qh = g_qkH + (size_t)n * CK * Qn;
    const __half* ql = g_qkL + (size_t)n * CK * Qn;
    const __half* mh = g_mkH + (size_t)n * CK * Mn;
    const int warpQ = (wid & 1) * 32, warpM = (wid >> 1) * 32;

    #pragma unroll
    for (int kt = 0; kt < 4; ++kt) {
        #pragma unroll
        for (int p = 0; p < 2; ++p) {
            int o = tid + p * 256;
            int row = o >> 4, col = (o & 15) * 4;
            size_t so = (size_t)(kt * 32 + row) * Qn + qB + col;
            cpa8(&SqH[kt][row * PQ1 + col], qh + so);
            cpa8(&SqL[kt][row * PQ1 + col], ql + so);
        }
        #pragma unroll
        for (int p = 0; p < 2; ++p) {
            int o = tid + p * 256;
            int row = o >> 4, col = (o & 15) * 8;
            size_t so = (size_t)(kt * 32 + row) * Mn + mB + col;
            cpa16(&SmH[kt][row * PM1 + col], mh + so);
        }
        CP_COMMIT();
    }

    float acc[2][4][4] = {};

    #pragma unroll
    for (int kt = 0; kt < 4; ++kt) {
        if      (kt == 0) asm volatile("cp.async.wait_group 3;");
        else if (kt == 1) asm volatile("cp.async.wait_group 2;");
        else if (kt == 2) asm volatile("cp.async.wait_group 1;");
        else              asm volatile("cp.async.wait_group 0;");
        __syncthreads();
        const __half* sqh = SqH[kt];
        const __half* sql = SqL[kt];
        const __half* smh = SmH[kt];

        #pragma unroll
        for (int kk = 0; kk < 32; kk += 16) {
            uint32_t aH[2][4], aL[2][4], bH[4][2];
            const int ar = kk + ((lane >> 4) << 3) + (lane & 7);
            const int acs = ((lane >> 3) & 1) << 3;
            #pragma unroll
            for (int i = 0; i < 2; ++i) {
                int col = warpQ + i * 16 + acs;
                ldsm4t(aH[i], s2u(sqh + ar * PQ1 + col));
                ldsm4t(aL[i], s2u(sql + ar * PQ1 + col));
            }
            const int br = kk + (((lane >> 3) & 1) << 3) + (lane & 7);
            const int bcs = (lane >> 4) << 3;
            #pragma unroll
            for (int jj = 0; jj < 2; ++jj) {
                uint32_t r[4];
                int col = warpM + jj * 16 + bcs;
                ldsm4t(r, s2u(smh + br * PM1 + col));
                bH[jj*2][0] = r[0]; bH[jj*2][1] = r[1];
                bH[jj*2+1][0] = r[2]; bH[jj*2+1][1] = r[3];
            }
            #pragma unroll
            for (int i = 0; i < 2; ++i)
                #pragma unroll
                for (int j = 0; j < 4; ++j) {
                    hmma(acc[i][j], aH[i], bH[j]);
                    hmma(acc[i][j], aL[i], bH[j]);
                }
        }
    }

    const int g = lane >> 2, tg = lane & 3;
    __half* pp = g_p + (size_t)n * QM;
    #pragma unroll
    for (int j = 0; j < 4; ++j) {
        int m0 = mB + warpM + j * 8 + tg * 2;
        bool mval = m0 < Mn;
        float2 cs = make_float2(0.f, 0.f);
        #pragma unroll
        for (int i = 0; i < 2; ++i) {
            int q0 = qB + warpQ + i * 16 + g;
            __half2 h01 = __float2half2_rn(0.f), h23 = __float2half2_rn(0.f);
            if (q0 < Qn) {
                h01 = __floats2half2_rn(__expf(acc[i][j][0] * SCALE),
                                        __expf(acc[i][j][1] * SCALE));
                if (mval) *reinterpret_cast<__half2*>(pp + (size_t)q0 * Mn + m0) = h01;
            }
            if (q0 + 8 < Qn) {
                h23 = __floats2half2_rn(__expf(acc[i][j][2] * SCALE),
                                        __expf(acc[i][j][3] * SCALE));
                if (mval) *reinterpret_cast<__half2*>(pp + (size_t)(q0 + 8) * Mn + m0) = h23;
            }
            float2 f01 = __half22float2(h01), f23 = __half22float2(h23);
            cs.x += f01.x + f23.x;
            cs.y += f01.y + f23.y;
        }
        cs.x += __shfl_xor_sync(0xffffffffu, cs.x, 4);
        cs.x += __shfl_xor_sync(0xffffffffu, cs.x, 8);
        cs.x += __shfl_xor_sync(0xffffffffu, cs.x, 16);
        cs.y += __shfl_xor_sync(0xffffffffu, cs.y, 4);
        cs.y += __shfl_xor_sync(0xffffffffu, cs.y, 8);
        cs.y += __shfl_xor_sync(0xffffffffu, cs.y, 16);
        if (lane < 4 && mval) {
            atomicAdd(&g_sum[n * Mn + m0], cs.x);
            atomicAdd(&g_sum[n * Mn + m0 + 1], cs.y);
        }
    }
}

// ---------------------------------------------------------------------------
// K2w: winv = 1/sum
// ---------------------------------------------------------------------------
__global__ void k2_winv() {
    int i = blockIdx.x * blockDim.x + threadIdx.x;
    if (i < Nn * Mn) g_winv[i] = 1.f / g_sum[i];
}

// ---------------------------------------------------------------------------
// K2: g_mvh[n,c,m] = half( mv[n,c,m] * winv[n,m] )
// ---------------------------------------------------------------------------
__global__ void k2_scale(const float4* __restrict__ mv) {
    int i = blockIdx.x * blockDim.x + threadIdx.x;
    if (i >= (Nn * CV * Mn) / 4) return;
    size_t flat = (size_t)i * 4;
    int n = (int)(flat / ((size_t)CV * Mn));
    int m = (int)(flat % Mn);
    float4 v = mv[i];
    float4 w = *reinterpret_cast<const float4*>(g_winv + n * Mn + m);
    __half2* d = reinterpret_cast<__half2*>(g_mvh + flat);
    d[0] = __floats2half2_rn(v.x * w.x, v.y * w.y);
    d[1] = __floats2half2_rn(v.z * w.z, v.w * w.w);
}

// ---------------------------------------------------------------------------
// K3: out[n,512+c,q] = sum_m mvh[n,c,m] * g_p[n,q,m]
// Block tile 128(c) x 256(q), k(m) chunks of 32 (225 iters), 3-stage cp.async.
// 512 threads = 16 warps = 2(c) x 8(q), warp tile 64c x 32q.
// Grid 4(q) x 4(c) x 8(n) = 128 CTAs -> 1 CTA/SM, single wave.
// ---------------------------------------------------------------------------
#define PA 40
#define S3 3
#define A_HALFS (128 * PA)                  // 5120
#define P_HALFS (256 * PA)                  // 10240
#define STAGE_HALFS (A_HALFS + P_HALFS)     // 15360 halfs = 30720 B
#define K3_SMEM (S3 * STAGE_HALFS * 2)      // 92160 B

__global__ void __launch_bounds__(512) k3_map(float* __restrict__ out) {
    extern __shared__ __align__(16) __half sm[];

    const int tid = threadIdx.x, lane = tid & 31, wid = tid >> 5;
    const int n = blockIdx.z, qB = blockIdx.x * 256, cB = blockIdx.y * 128;
    const __half* av = g_mvh + (size_t)n * CV * Mn + (size_t)cB * Mn;
    const __half* pp = g_p + (size_t)n * QM;
    const int warpC = (wid & 1) * 64, warpQ = (wid >> 1) * 32;

    // load coords: A = 512 16B-chunks (1/thread), P = 1024 (2/thread)
    const int ar = tid >> 2, ac = (tid & 3) * 8;
    const int pr2 = (tid + 512) >> 2, pc2 = ((tid + 512) & 3) * 8;
    const bool pv1 = (qB + ar) < Qn;
    const bool pv2 = (qB + pr2) < Qn;

    float acc[4][4][4] = {};

    auto load_stage = [&](int it, int st) {
        const int mO = it * 32;
        __half* a = sm + st * STAGE_HALFS;
        __half* p = a + A_HALFS;
        cpa16(a + ar * PA + ac, av + (size_t)ar * Mn + mO + ac);
        cpa16z(p + ar * PA + ac,   pp + (size_t)(qB + ar) * Mn + mO + ac,   pv1);
        cpa16z(p + pr2 * PA + pc2, pp + (size_t)(qB + pr2) * Mn + mO + pc2, pv2);
        CP_COMMIT();
    };

    load_stage(0, 0);
    load_stage(1, 1);

    for (int it = 0; it < Mn / 32; ++it) {
        asm volatile("cp.async.wait_group %0;" :: "n"(1));
        __syncthreads();
        const int st = it % S3;
        const __half* as = sm + st * STAGE_HALFS;
        const __half* ps = as + A_HALFS;

        #pragma unroll
        for (int kk = 0; kk < 32; kk += 16) {
            uint32_t a[4][4], b[4][2];
            #pragma unroll
            for (int i = 0; i < 4; ++i)
                ldsm4(a[i], s2u(as + (warpC + i * 16 + (lane & 15)) * PA
                                   + kk + ((lane >> 4) << 3)));
            #pragma unroll
            for (int jj = 0; jj < 2; ++jj) {
                uint32_t r[4];
                ldsm4(r, s2u(ps + (warpQ + jj * 16 + ((lane >> 4) << 3) + (lane & 7)) * PA
                                + kk + (((lane >> 3) & 1) << 3)));
                b[jj*2][0] = r[0]; b[jj*2][1] = r[1];
                b[jj*2+1][0] = r[2]; b[jj*2+1][1] = r[3];
            }
            #pragma unroll
            for (int i = 0; i < 4; ++i)
                #pragma unroll
                for (int j = 0; j < 4; ++j)
                    hmma(acc[i][j], a[i], b[j]);
        }

        int nx = it + 2;
        if (nx < Mn / 32) {
            __syncthreads();   // all warps done reading slot (nx % S3) from it-1
            load_stage(nx, nx % S3);
        }
    }

    const int g = lane >> 2, tg = lane & 3;
    float* op = out + (size_t)n * OUT_PER_N;
    #pragma unroll
    for (int i = 0; i < 4; ++i) {
        int ch = 512 + cB + warpC + i * 16 + g;
        #pragma unroll
        for (int j = 0; j < 4; ++j) {
            int q = qB + warpQ + j * 8 + tg * 2;
            if (q < Qn) {
                *reinterpret_cast<float2*>(op + (size_t)ch * Qn + q) =
                    make_float2(acc[i][j][0], acc[i][j][1]);
                *reinterpret_cast<float2*>(op + (size_t)(ch + 8) * Qn + q) =
                    make_float2(acc[i][j][2], acc[i][j][3]);
            }
        }
    }
}

// ---------------------------------------------------------------------------
extern "C" void kernel_launch(void* const* d_in, const int* in_sizes, int n_in,
                              void* d_out, int out_size) {
    const float* q_key = (const float*)d_in[0];
    const float* q_val = (const float*)d_in[1];
    const float* m_key = (const float*)d_in[2];
    const float* m_val = (const float*)d_in[3];
    float* out = (float*)d_out;

    {   // k_prep: qk split + mk cvt + q_val copy + g_sum zero
        int total = QK4 + MK4 + QV4;   // 2,995,200
        k_prep<<<(total + 255) / 256, 256>>>(
            reinterpret_cast<const float4*>(q_key),
            reinterpret_cast<const float4*>(m_key),
            reinterpret_cast<const float4*>(q_val), out);
    }
    {   // K1: affinity GEMM (x2) + exp + fused column sums
        dim3 grid((Mn + 127) / 128, (Qn + 63) / 64, Nn);   // 57 x 15 x 8
        k1_aff<<<grid, 256>>>();
    }
    {   // K2w: winv = 1/sum
        k2_winv<<<(Nn * Mn + 255) / 256, 256>>>();
    }
    {   // K2: mvh = half(mv * winv)
        int f4 = (Nn * CV * Mn) / 4;
        k2_scale<<<(f4 + 255) / 256, 256>>>(reinterpret_cast<const float4*>(m_val));
    }
    {   // K3: mapped GEMM (pipelined, 128c x 256q tiles, 512 threads)
        cudaFuncSetAttribute(k3_map, cudaFuncAttributeMaxDynamicSharedMemorySize, K3_SMEM);
        dim3 grid(4, CV / 128, Nn);                        // 4 x 4 x 8 = 128 CTAs
        k3_map<<<grid, 512, K3_SMEM>>>(out);
    }
}

// round 11
// speedup vs baseline: 1.0958x; 1.0958x over previous
#include <cuda_runtime.h>
#include <cuda_fp16.h>
#include <cstdint>

#define Nn 8
#define CK 128
#define CV 512
#define Qn 900
#define Mn 7200
#define QM (Qn*Mn)
#define OUT_PER_N (1024*900)
#define SCALE 0.08838834764831845f   // 1/sqrt(128)

// Scratch (__device__ globals; allocation-free rule)
__device__ __align__(16) __half g_p[(size_t)Nn * QM + 64];        // exp(aff) fp16
__device__ __align__(16) __half g_mvh[(size_t)Nn * CV * Mn + 64]; // mv * winv fp16
__device__ __align__(16) __half g_qkH[Nn * CK * Qn + 64];
__device__ __align__(16) __half g_mkH[Nn * CK * Mn + 128];
__device__ float g_sum[Nn * Mn];
__device__ float g_winv[Nn * Mn];

__device__ __forceinline__ uint32_t s2u(const void* p) {
    return (uint32_t)__cvta_generic_to_shared(p);
}
__device__ __forceinline__ void ldsm4(uint32_t* r, uint32_t a) {
    asm volatile("ldmatrix.sync.aligned.m8n8.x4.shared.b16 {%0,%1,%2,%3},[%4];"
                 : "=r"(r[0]), "=r"(r[1]), "=r"(r[2]), "=r"(r[3]) : "r"(a));
}
__device__ __forceinline__ void ldsm4t(uint32_t* r, uint32_t a) {
    asm volatile("ldmatrix.sync.aligned.m8n8.x4.trans.shared.b16 {%0,%1,%2,%3},[%4];"
                 : "=r"(r[0]), "=r"(r[1]), "=r"(r[2]), "=r"(r[3]) : "r"(a));
}
__device__ __forceinline__ void hmma(float* d, const uint32_t* a, const uint32_t* b) {
    asm volatile("mma.sync.aligned.m16n8k16.row.col.f32.f16.f16.f32 "
                 "{%0,%1,%2,%3},{%4,%5,%6,%7},{%8,%9},{%0,%1,%2,%3};"
                 : "+f"(d[0]), "+f"(d[1]), "+f"(d[2]), "+f"(d[3])
                 : "r"(a[0]), "r"(a[1]), "r"(a[2]), "r"(a[3]), "r"(b[0]), "r"(b[1]));
}
__device__ __forceinline__ void cpa16(void* dst, const void* src) {
    asm volatile("cp.async.cg.shared.global [%0],[%1],16;" :: "r"(s2u(dst)), "l"(src));
}
__device__ __forceinline__ void cpa16z(void* dst, const void* src, bool pred) {
    int sz = pred ? 16 : 0;   // src-size 0 -> 16B zero-fill
    asm volatile("cp.async.cg.shared.global [%0],[%1],16,%2;" :: "r"(s2u(dst)), "l"(src), "r"(sz));
}
__device__ __forceinline__ void cpa8(void* dst, const void* src) {
    asm volatile("cp.async.ca.shared.global [%0],[%1],8;" :: "r"(s2u(dst)), "l"(src));
}
#define CP_COMMIT() asm volatile("cp.async.commit_group;")

// ---------------------------------------------------------------------------
// k_prep: qk fp16 cvt, mk fp16 cvt, q_val copy, g_sum zero — one launch.
// ---------------------------------------------------------------------------
#define QK4 (Nn * CK * Qn / 4)          // 230400
#define MK4 (Nn * CK * Mn / 4)          // 1843200
#define QV4 (Nn * CV * Qn / 4)          // 921600
__global__ void k_prep(const float4* __restrict__ qk, const float4* __restrict__ mk,
                       const float4* __restrict__ qv, float* __restrict__ out) {
    int i = blockIdx.x * blockDim.x + threadIdx.x;
    if (i < Nn * Mn) g_sum[i] = 0.f;
    if (i < QK4) {
        float4 v = qk[i];
        __half2* dh = reinterpret_cast<__half2*>(g_qkH + (size_t)i * 4);
        dh[0] = __floats2half2_rn(v.x, v.y);
        dh[1] = __floats2half2_rn(v.z, v.w);
    } else if (i < QK4 + MK4) {
        int j = i - QK4;
        float4 v = mk[j];
        __half2* dh = reinterpret_cast<__half2*>(g_mkH + (size_t)j * 4);
        dh[0] = __floats2half2_rn(v.x, v.y);
        dh[1] = __floats2half2_rn(v.z, v.w);
    } else if (i < QK4 + MK4 + QV4) {
        int j = i - QK4 - MK4;
        int n = j / ((CV * Qn) / 4);
        int r = j - n * ((CV * Qn) / 4);
        float4 v = qv[j];
        *reinterpret_cast<float4*>(out + (size_t)n * OUT_PER_N + (size_t)r * 4) = v;
    }
}

// ---------------------------------------------------------------------------
// K1: g_p = exp(SCALE * qk^T mk), plain fp16, cp.async (4 k-chunks prefetched).
// Fused column sums of the ROUNDED fp16 values.
// Block 64(q) x 128(m); 8 warps = 2(q) x 4(m).
// ---------------------------------------------------------------------------
#define PQ1 72
#define PM1 136
__global__ void __launch_bounds__(256) k1_aff() {
    __shared__ __half SqH[4][32 * PQ1];
    __shared__ __half SmH[4][32 * PM1];

    const int tid = threadIdx.x, lane = tid & 31, wid = tid >> 5;
    const int n = blockIdx.z, qB = blockIdx.y * 64, mB = blockIdx.x * 128;
    const __half* qh = g_qkH + (size_t)n * CK * Qn;
    const __half* mh = g_mkH + (size_t)n * CK * Mn;
    const int warpQ = (wid & 1) * 32, warpM = (wid >> 1) * 32;

    #pragma unroll
    for (int kt = 0; kt < 4; ++kt) {
        #pragma unroll
        for (int p = 0; p < 2; ++p) {
            int o = tid + p * 256;
            int row = o >> 4, col = (o & 15) * 4;
            size_t so = (size_t)(kt * 32 + row) * Qn + qB + col;
            cpa8(&SqH[kt][row * PQ1 + col], qh + so);
        }
        #pragma unroll
        for (int p = 0; p < 2; ++p) {
            int o = tid + p * 256;
            int row = o >> 4, col = (o & 15) * 8;
            size_t so = (size_t)(kt * 32 + row) * Mn + mB + col;
            cpa16(&SmH[kt][row * PM1 + col], mh + so);
        }
        CP_COMMIT();
    }

    float acc[2][4][4] = {};

    #pragma unroll
    for (int kt = 0; kt < 4; ++kt) {
        if      (kt == 0) asm volatile("cp.async.wait_group 3;");
        else if (kt == 1) asm volatile("cp.async.wait_group 2;");
        else if (kt == 2) asm volatile("cp.async.wait_group 1;");
        else              asm volatile("cp.async.wait_group 0;");
        __syncthreads();
        const __half* sqh = SqH[kt];
        const __half* smh = SmH[kt];

        #pragma unroll
        for (int kk = 0; kk < 32; kk += 16) {
            uint32_t aH[2][4], bH[4][2];
            const int ar = kk + ((lane >> 4) << 3) + (lane & 7);
            const int acs = ((lane >> 3) & 1) << 3;
            #pragma unroll
            for (int i = 0; i < 2; ++i) {
                int col = warpQ + i * 16 + acs;
                ldsm4t(aH[i], s2u(sqh + ar * PQ1 + col));
            }
            const int br = kk + (((lane >> 3) & 1) << 3) + (lane & 7);
            const int bcs = (lane >> 4) << 3;
            #pragma unroll
            for (int jj = 0; jj < 2; ++jj) {
                uint32_t r[4];
                int col = warpM + jj * 16 + bcs;
                ldsm4t(r, s2u(smh + br * PM1 + col));
                bH[jj*2][0] = r[0]; bH[jj*2][1] = r[1];
                bH[jj*2+1][0] = r[2]; bH[jj*2+1][1] = r[3];
            }
            #pragma unroll
            for (int i = 0; i < 2; ++i)
                #pragma unroll
                for (int j = 0; j < 4; ++j)
                    hmma(acc[i][j], aH[i], bH[j]);
        }
    }

    // Epilogue: exp -> fp16 round -> store; column sums of ROUNDED values
    const int g = lane >> 2, tg = lane & 3;
    __half* pp = g_p + (size_t)n * QM;
    #pragma unroll
    for (int j = 0; j < 4; ++j) {
        int m0 = mB + warpM + j * 8 + tg * 2;
        bool mval = m0 < Mn;
        float2 cs = make_float2(0.f, 0.f);
        #pragma unroll
        for (int i = 0; i < 2; ++i) {
            int q0 = qB + warpQ + i * 16 + g;
            __half2 h01 = __float2half2_rn(0.f), h23 = __float2half2_rn(0.f);
            if (q0 < Qn) {
                h01 = __floats2half2_rn(__expf(acc[i][j][0] * SCALE),
                                        __expf(acc[i][j][1] * SCALE));
                if (mval) *reinterpret_cast<__half2*>(pp + (size_t)q0 * Mn + m0) = h01;
            }
            if (q0 + 8 < Qn) {
                h23 = __floats2half2_rn(__expf(acc[i][j][2] * SCALE),
                                        __expf(acc[i][j][3] * SCALE));
                if (mval) *reinterpret_cast<__half2*>(pp + (size_t)(q0 + 8) * Mn + m0) = h23;
            }
            float2 f01 = __half22float2(h01), f23 = __half22float2(h23);
            cs.x += f01.x + f23.x;
            cs.y += f01.y + f23.y;
        }
        cs.x += __shfl_xor_sync(0xffffffffu, cs.x, 4);
        cs.x += __shfl_xor_sync(0xffffffffu, cs.x, 8);
        cs.x += __shfl_xor_sync(0xffffffffu, cs.x, 16);
        cs.y += __shfl_xor_sync(0xffffffffu, cs.y, 4);
        cs.y += __shfl_xor_sync(0xffffffffu, cs.y, 8);
        cs.y += __shfl_xor_sync(0xffffffffu, cs.y, 16);
        if (lane < 4 && mval) {
            atomicAdd(&g_sum[n * Mn + m0], cs.x);
            atomicAdd(&g_sum[n * Mn + m0 + 1], cs.y);
        }
    }
}

// ---------------------------------------------------------------------------
// K2w: winv = 1/sum
// ---------------------------------------------------------------------------
__global__ void k2_winv() {
    int i = blockIdx.x * blockDim.x + threadIdx.x;
    if (i < Nn * Mn) g_winv[i] = 1.f / g_sum[i];
}

// ---------------------------------------------------------------------------
// K2: g_mvh[n,c,m] = half( mv[n,c,m] * winv[n,m] )
// ---------------------------------------------------------------------------
__global__ void k2_scale(const float4* __restrict__ mv) {
    int i = blockIdx.x * blockDim.x + threadIdx.x;
    if (i >= (Nn * CV * Mn) / 4) return;
    size_t flat = (size_t)i * 4;
    int n = (int)(flat / ((size_t)CV * Mn));
    int m = (int)(flat % Mn);
    float4 v = mv[i];
    float4 w = *reinterpret_cast<const float4*>(g_winv + n * Mn + m);
    __half2* d = reinterpret_cast<__half2*>(g_mvh + flat);
    d[0] = __floats2half2_rn(v.x * w.x, v.y * w.y);
    d[1] = __floats2half2_rn(v.z * w.z, v.w * w.w);
}

// ---------------------------------------------------------------------------
// K3: out[n,512+c,q] = sum_m mvh[n,c,m] * g_p[n,q,m]
// Block 128(c) x 128(q), k(m) chunks of 32 (225 iters), 4-stage cp.async.
// 8 warps = 2(c) x 4(q), warp tile 64c x 32q.  (proven R8 config)
// ---------------------------------------------------------------------------
#define PA 40
#define STG 4
__global__ void __launch_bounds__(256) k3_map(float* __restrict__ out) {
    __shared__ __half As[STG][128 * PA];
    __shared__ __half Ps[STG][128 * PA];

    const int tid = threadIdx.x, lane = tid & 31, wid = tid >> 5;
    const int n = blockIdx.z, qB = blockIdx.x * 128, cB = blockIdx.y * 128;
    const __half* av = g_mvh + (size_t)n * CV * Mn + (size_t)cB * Mn;
    const __half* pp = g_p + (size_t)n * QM;
    const int warpC = (wid & 1) * 64, warpQ = (wid >> 1) * 32;

    const int arow = tid >> 1;
    const int acol = (tid & 1) * 16;
    const bool pqv = (qB + arow) < Qn;

    float acc[4][4][4] = {};

    auto load_stage = [&](int it, int st) {
        const int mO = it * 32;
        cpa16(&As[st][arow * PA + acol],     av + (size_t)arow * Mn + mO + acol);
        cpa16(&As[st][arow * PA + acol + 8], av + (size_t)arow * Mn + mO + acol + 8);
        cpa16z(&Ps[st][arow * PA + acol],     pp + (size_t)(qB + arow) * Mn + mO + acol, pqv);
        cpa16z(&Ps[st][arow * PA + acol + 8], pp + (size_t)(qB + arow) * Mn + mO + acol + 8, pqv);
        CP_COMMIT();
    };

    #pragma unroll
    for (int s = 0; s < STG - 1; ++s) load_stage(s, s);

    for (int it = 0; it < Mn / 32; ++it) {
        asm volatile("cp.async.wait_group %0;" :: "n"(STG - 2));
        __syncthreads();
        const __half* as = As[it & (STG - 1)];
        const __half* ps = Ps[it & (STG - 1)];

        #pragma unroll
        for (int kk = 0; kk < 32; kk += 16) {
            uint32_t a[4][4], b[4][2];
            #pragma unroll
            for (int i = 0; i < 4; ++i)
                ldsm4(a[i], s2u(as + (warpC + i * 16 + (lane & 15)) * PA
                                   + kk + ((lane >> 4) << 3)));
            #pragma unroll
            for (int jj = 0; jj < 2; ++jj) {
                uint32_t r[4];
                ldsm4(r, s2u(ps + (warpQ + jj * 16 + ((lane >> 4) << 3) + (lane & 7)) * PA
                                + kk + (((lane >> 3) & 1) << 3)));
                b[jj*2][0] = r[0]; b[jj*2][1] = r[1];
                b[jj*2+1][0] = r[2]; b[jj*2+1][1] = r[3];
            }
            #pragma unroll
            for (int i = 0; i < 4; ++i)
                #pragma unroll
                for (int j = 0; j < 4; ++j)
                    hmma(acc[i][j], a[i], b[j]);
        }

        int nx = it + STG - 1;
        if (nx < Mn / 32) load_stage(nx, nx & (STG - 1));
    }

    const int g = lane >> 2, tg = lane & 3;
    float* op = out + (size_t)n * OUT_PER_N;
    #pragma unroll
    for (int i = 0; i < 4; ++i) {
        int ch = 512 + cB + warpC + i * 16 + g;
        #pragma unroll
        for (int j = 0; j < 4; ++j) {
            int q = qB + warpQ + j * 8 + tg * 2;
            if (q < Qn) {
                *reinterpret_cast<float2*>(op + (size_t)ch * Qn + q) =
                    make_float2(acc[i][j][0], acc[i][j][1]);
                *reinterpret_cast<float2*>(op + (size_t)(ch + 8) * Qn + q) =
                    make_float2(acc[i][j][2], acc[i][j][3]);
            }
        }
    }
}

// ---------------------------------------------------------------------------
extern "C" void kernel_launch(void* const* d_in, const int* in_sizes, int n_in,
                              void* d_out, int out_size) {
    const float* q_key = (const float*)d_in[0];
    const float* q_val = (const float*)d_in[1];
    const float* m_key = (const float*)d_in[2];
    const float* m_val = (const float*)d_in[3];
    float* out = (float*)d_out;

    {   // k_prep: qk/mk fp16 cvt + q_val copy + g_sum zero
        int total = QK4 + MK4 + QV4;   // 2,995,200
        k_prep<<<(total + 255) / 256, 256>>>(
            reinterpret_cast<const float4*>(q_key),
            reinterpret_cast<const float4*>(m_key),
            reinterpret_cast<const float4*>(q_val), out);
    }
    {   // K1: affinity GEMM (fp16) + exp + fused column sums
        dim3 grid((Mn + 127) / 128, (Qn + 63) / 64, Nn);   // 57 x 15 x 8
        k1_aff<<<grid, 256>>>();
    }
    {   // K2w: winv = 1/sum
        k2_winv<<<(Nn * Mn + 255) / 256, 256>>>();
    }
    {   // K2: mvh = half(mv * winv)
        int f4 = (Nn * CV * Mn) / 4;
        k2_scale<<<(f4 + 255) / 256, 256>>>(reinterpret_cast<const float4*>(m_val));
    }
    {   // K3: mapped GEMM (pipelined, 128x128 tiles — proven R8 config)
        dim3 grid((Qn + 127) / 128, CV / 128, Nn);         // 8 x 4 x 8
        k3_map<<<grid, 256>>>(out);
    }
}